// round 12
// baseline (speedup 1.0000x reference)
#include <cuda_runtime.h>
#include <math.h>

typedef unsigned long long u64;

#define FMA2(d, a, b, c) \
    asm("fma.rn.f32x2 %0, %1, %2, %3;" : "=l"(d) : "l"(a), "l"(b), "l"(c))
#define PACK2(d, lo, hi) \
    asm("mov.b64 %0, {%1, %2};" : "=l"(d) : "f"(lo), "f"(hi))
#define UNPACK2(lo, hi, d) \
    asm("mov.b64 {%0, %1}, %2;" : "=f"(lo), "=f"(hi) : "l"(d))
#define LDS_V2B64(a, b, addr) \
    asm volatile("ld.shared.v2.b64 {%0, %1}, [%2];" : "=l"(a), "=l"(b) : "r"(addr))

#define N_IN   4096
#define N_OUT  1024
#define BATCH  16
#define E_MAX  81920

__device__ float g_featT2[N_IN * 512];                 // [n][c*16+b]
__device__ int   g_is64;
__device__ int   g_seg[E_MAX];
__device__ int   g_src[E_MAX];

// ---------------- phase -1: dtype detect + index normalize ------------------
__global__ void detect_idx(const int* __restrict__ idx32, int E) {
    __shared__ int any;
    if (threadIdx.x == 0) any = 0;
    __syncthreads();
    int n = min(E, 512);
    int local = 0;
    for (int m = threadIdx.x; m < n; m += 256)
        local |= idx32[4 * m + 1] | idx32[4 * m + 3];
    if (local) atomicOr(&any, 1);
    __syncthreads();
    if (threadIdx.x == 0) g_is64 = any ? 0 : 1;
}

__global__ void convert_idx(const int* __restrict__ idx32, int E) {
    int m = blockIdx.x * 256 + threadIdx.x;
    if (m >= E) return;
    if (g_is64) { g_seg[m] = idx32[4 * m];     g_src[m] = idx32[4 * m + 2]; }
    else        { g_seg[m] = idx32[2 * m];     g_src[m] = idx32[2 * m + 1]; }
}

// ---------------- zero-init output (poisoned 0xAA; empty segments must be 0)
__global__ void zero_out(float4* __restrict__ out) {
    out[blockIdx.x * 256 + threadIdx.x] = make_float4(0.f, 0.f, 0.f, 0.f);
}

// ---------------- phase 0: tiled permute feat[b][c][n] -> featT2[n][c*16+b]
__global__ void prep_featT(const float* __restrict__ feat) {
    __shared__ float tile[32][33];
    int n0  = blockIdx.x * 32;
    int cb0 = blockIdx.y * 32;
    int tx = threadIdx.x, ty = threadIdx.y;       // 32 x 8
    #pragma unroll
    for (int i = ty; i < 32; i += 8) {
        int cb = cb0 + i;
        int row = (cb & 15) * 32 + (cb >> 4);     // b*32 + c
        tile[i][tx] = feat[(size_t)row * N_IN + n0 + tx];
    }
    __syncthreads();
    #pragma unroll
    for (int i = ty; i < 32; i += 8)
        g_featT2[(size_t)(n0 + i) * 512 + cb0 + tx] = tile[tx][i];
}

// ---------------- phase A (fused; cp.async-prefetched gathers) -------------
// 256 threads, 16 edges/block, 2 blocks/SM. smem (floats):
//  h1 [16][64]      @0      (1024)
//  h2t[64][20]      @1024   (1280)
//  W2s[64][64]      @2304   (4096)
//  g  [16][16][36]  @6400   (9216)  <- first 4608 overlaid by vals[16][264]
//  filt[8][32][36]  @15616  (9216)
//  locs[32+pad]     @24832
//  goff[512] int    @24896
//  keys[512] int    @25408
//  gstart[2][66]+ng @25920  (134)
#define OFF_H1   0
#define OFF_H2T  1024
#define OFF_W2S  2304
#define OFF_G    6400
#define OFF_F    15616
#define OFF_LOCS 24832
#define OFF_GOFF 24896
#define OFF_KEYS 25408
#define OFF_GST  25920
#define SMEM_A_FLOATS 26056
#define SMEM_A_BYTES  (SMEM_A_FLOATS * 4)
#define VROW 264

__global__ __launch_bounds__(256, 2) void quad_main(
    const float* __restrict__ W1, const float* __restrict__ W2,
    const float* __restrict__ W3, const float* __restrict__ eval_locs,
    float* __restrict__ out, int E)
{
    extern __shared__ float sm[];
    float* h1_s   = sm + OFF_H1;
    float* h2t    = sm + OFF_H2T;
    float* W2s    = sm + OFF_W2S;
    float* g_s    = sm + OFF_G;
    float* vals_s = sm + OFF_G;        // overlay (first 4224 floats)
    float* f_s    = sm + OFF_F;
    float* locs   = sm + OFF_LOCS;
    int*   goff   = (int*)(sm + OFF_GOFF);
    int*   keys_s = (int*)(sm + OFF_KEYS);
    int*   gst    = (int*)(sm + OFF_GST);       // [2][66]
    int*   ng_s   = (int*)(sm + OFF_GST) + 132; // [2]
    const unsigned smb = (unsigned)__cvta_generic_to_shared(sm);

    const int t   = threadIdx.x;
    const int e0  = blockIdx.x * 16;
    const int net = min(16, E - e0);
    const int mb  = blockIdx.x * 512;   // flat vals base for this block

    if (t < 2 * net) locs[t] = eval_locs[2 * e0 + t];

    // stage W2 into smem (coalesced, once per block)
    #pragma unroll
    for (int r = 0; r < 16; r++)
        W2s[t + 256 * r] = W2[t + 256 * r];

    // gather offsets per (e, ci) AND scramble keys per flat pos p
    #pragma unroll
    for (int r = 0; r < 2; r++) {
        int p = t + 256 * r;              // 0..511
        int key = -1;
        int off = 0;
        if (p < net * 32) {
            int m  = mb + p;
            int c  = m / E;
            int rr = m - c * E;
            off = g_src[rr] * 512 + c * 16;
            key = (c << 10) + g_seg[rr];
        }
        goff[p]   = off;
        keys_s[p] = key;
    }
    __syncthreads();

    // ---- prefetch ALL 16 edges' gathers via cp.async (latency hides under MLP)
    #pragma unroll
    for (int r = 0; r < 32; r++) {
        int i  = t + 256 * r;             // 0..8191
        int p8 = i >> 4;                  // (e,ci) 0..511
        int b  = i & 15;
        int e  = p8 >> 5, ci = p8 & 31;
        unsigned dst = smb + (OFF_G + e * 576 + b * 36 + ci) * 4u;
        const float* src = &g_featT2[goff[p8] + b];
        int sz = (e < net) ? 4 : 0;       // padded edges zero-fill
        asm volatile("cp.async.ca.shared.global [%0], [%1], 4, %2;"
                     :: "r"(dst), "l"(src), "r"(sz) : "memory");
    }
    asm volatile("cp.async.commit_group;" ::: "memory");

    // warps 0/1: run-boundary scan of keys for sub 0/1
    if (t < 64) {
        int sub  = t >> 5, l = t & 31;
        int base = sub * 256;
        int cnt = 0, st[8];
        #pragma unroll
        for (int i = 0; i < 8; i++) {
            int p = base + l * 8 + i;
            int kprev = (p == base) ? 0x7fffffff : keys_s[p - 1];
            if (keys_s[p] != kprev) st[cnt++] = p;
        }
        unsigned off = (unsigned)cnt;
        #pragma unroll
        for (int d = 1; d < 32; d <<= 1) {
            unsigned v = __shfl_up_sync(0xffffffffu, off, d);
            if (l >= d) off += v;
        }
        int excl = (int)off - cnt;
        for (int i = 0; i < cnt; i++) gst[sub * 66 + excl + i] = st[i];
        if (l == 31) { ng_s[sub] = (int)off; gst[sub * 66 + (int)off] = base + 256; }
    }

    // h1[e][j] = sin(loc_e . W1[:,j])   (0 for padded edges)
    #pragma unroll
    for (int r = 0; r < 4; r++) {
        int id = t + 256 * r;             // 0..1023
        int e = id >> 6, j = id & 63;
        float v = 0.f;
        if (e < net)
            v = __sinf(locs[2 * e] * W1[j] + locs[2 * e + 1] * W1[64 + j]);
        h1_s[id] = v;
    }
    __syncthreads();

    // ---- h2 (f32x2): thread owns (e = t>>4, cols j0..j0+3); writes h2t[j][e]
    {
        const int e  = t >> 4;
        const int j0 = (t & 15) * 4;
        u64 aA = 0ull, aB = 0ull;
        #pragma unroll
        for (int k4 = 0; k4 < 64; k4 += 4) {
            float4 hv = *(const float4*)&h1_s[e * 64 + k4];
            float hs[4] = {hv.x, hv.y, hv.z, hv.w};
            #pragma unroll
            for (int kk = 0; kk < 4; kk++) {
                u64 hh; PACK2(hh, hs[kk], hs[kk]);
                u64 w01, w23;
                LDS_V2B64(w01, w23, smb + (OFF_W2S + (k4 + kk) * 64 + j0) * 4);
                FMA2(aA, hh, w01, aA);
                FMA2(aB, hh, w23, aB);
            }
        }
        float s0, s1, s2, s3;
        UNPACK2(s0, s1, aA);
        UNPACK2(s2, s3, aB);
        s0 = __sinf(s0); s1 = __sinf(s1); s2 = __sinf(s2); s3 = __sinf(s3);
        if (e >= net) { s0 = s1 = s2 = s3 = 0.f; }
        h2t[(j0 + 0) * 20 + e] = s0;
        h2t[(j0 + 1) * 20 + e] = s1;
        h2t[(j0 + 2) * 20 + e] = s2;
        h2t[(j0 + 3) * 20 + e] = s3;
    }
    __syncthreads();

    // ---- filter gen (f32x2): thread owns 4 cols {4t..4t+3}, all 16 edges.
    u64 acc[4][8];
    #pragma unroll
    for (int c = 0; c < 4; c++)
        #pragma unroll
        for (int p = 0; p < 8; p++) acc[c][p] = 0ull;

    const float4* w3p4 = (const float4*)W3 + t;     // row stride 256 float4
    float4 wcur = w3p4[0];

    #pragma unroll 8
    for (int k = 0; k < 64; k++) {
        float4 wnext = (k < 63) ? w3p4[(k + 1) * 256] : wcur;
        u64 wa, wb, wc, wd;
        PACK2(wa, wcur.x, wcur.x);
        PACK2(wb, wcur.y, wcur.y);
        PACK2(wc, wcur.z, wcur.z);
        PACK2(wd, wcur.w, wcur.w);
        const unsigned ha = smb + (OFF_H2T + k * 20) * 4;
        u64 hp[8];
        LDS_V2B64(hp[0], hp[1], ha);
        LDS_V2B64(hp[2], hp[3], ha + 16);
        LDS_V2B64(hp[4], hp[5], ha + 32);
        LDS_V2B64(hp[6], hp[7], ha + 48);
        #pragma unroll
        for (int p = 0; p < 8; p++) {
            FMA2(acc[0][p], wa, hp[p], acc[0][p]);
            FMA2(acc[1][p], wb, hp[p], acc[1][p]);
            FMA2(acc[2][p], wc, hp[p], acc[2][p]);
            FMA2(acc[3][p], wd, hp[p], acc[3][p]);
        }
        wcur = wnext;
    }

    // all prefetched gathers must be in smem before apply
    asm volatile("cp.async.wait_group 0;" ::: "memory");

    // mappings
    const int fci = t >> 3;              // filt store: col 4t -> ci
    const int fco = (t & 7) * 4;
    const int ea  = t >> 5;              // apply: edge within sub (0..7)
    const int b0  = ((t >> 2) & 7) * 2;  //        2 batches
    const int j0  = (t & 3) * 8;         //        8 consecutive co

    #pragma unroll
    for (int sub = 0; sub < 2; sub++) {
        const int es0 = sub * 8;

        // store this sub's filters: edge pairs 4*sub..4*sub+3
        #pragma unroll
        for (int p = 0; p < 4; p++) {
            int pp = sub * 4 + p;
            float x0, x1, y0, y1, z0, z1, w0, w1;
            UNPACK2(x0, x1, acc[0][pp]);
            UNPACK2(y0, y1, acc[1][pp]);
            UNPACK2(z0, z1, acc[2][pp]);
            UNPACK2(w0, w1, acc[3][pp]);
            *(float4*)&f_s[(2 * p)     * 1152 + fci * 36 + fco] = make_float4(x0, y0, z0, w0);
            *(float4*)&f_s[(2 * p + 1) * 1152 + fci * 36 + fco] = make_float4(x1, y1, z1, w1);
        }
        __syncthreads();

        // apply (f32x2): 2 batches x 8 co per thread, one edge
        u64 a0[4] = {0ull, 0ull, 0ull, 0ull};
        u64 a1[4] = {0ull, 0ull, 0ull, 0ull};
        if (es0 + ea < net) {
            const float* gp0 = &g_s[(es0 + ea) * 576 + b0 * 36];
            const float* gp1 = gp0 + 36;
            const unsigned fpa = smb + (OFF_F + ea * 1152 + j0) * 4;
            #pragma unroll
            for (int ci4 = 0; ci4 < 32; ci4 += 4) {
                float4 gv0 = *(const float4*)&gp0[ci4];
                float4 gv1 = *(const float4*)&gp1[ci4];
                float g0v[4] = {gv0.x, gv0.y, gv0.z, gv0.w};
                float g1v[4] = {gv1.x, gv1.y, gv1.z, gv1.w};
                #pragma unroll
                for (int kk = 0; kk < 4; kk++) {
                    u64 f01, f23, f45, f67;
                    LDS_V2B64(f01, f23, fpa + (ci4 + kk) * 144);
                    LDS_V2B64(f45, f67, fpa + (ci4 + kk) * 144 + 16);
                    u64 d0; PACK2(d0, g0v[kk], g0v[kk]);
                    FMA2(a0[0], d0, f01, a0[0]);
                    FMA2(a0[1], d0, f23, a0[1]);
                    FMA2(a0[2], d0, f45, a0[2]);
                    FMA2(a0[3], d0, f67, a0[3]);
                    u64 d1; PACK2(d1, g1v[kk], g1v[kk]);
                    FMA2(a1[0], d1, f01, a1[0]);
                    FMA2(a1[1], d1, f23, a1[1]);
                    FMA2(a1[2], d1, f45, a1[2]);
                    FMA2(a1[3], d1, f67, a1[3]);
                }
            }
        }
        __syncthreads();   // all reads of g_s(sub) / f_s complete

        // dump vals to smem (overlay of g edges 0..7): vals[b][ea*32 + j0..+7]
        {
            float* vp0 = &vals_s[b0 * VROW + ea * 32 + j0];
            float* vp1 = vp0 + VROW;
            ulonglong2 s0a; s0a.x = a0[0]; s0a.y = a0[1];
            ulonglong2 s0b; s0b.x = a0[2]; s0b.y = a0[3];
            ulonglong2 s1a; s1a.x = a1[0]; s1a.y = a1[1];
            ulonglong2 s1b; s1b.x = a1[2]; s1b.y = a1[3];
            *(ulonglong2*)vp0       = s0a;
            *(ulonglong2*)(vp0 + 4) = s0b;
            *(ulonglong2*)vp1       = s1a;
            *(ulonglong2*)(vp1 + 4) = s1b;
        }
        __syncthreads();   // vals ready

        // segment reduce: one (b, group) per task -> single atomicAdd
        {
            const int ng = ng_s[sub];
            const int base = sub * 256;
            for (int task = t; task < 16 * ng; task += 256) {
                int b  = task / ng;
                int gi = task - b * ng;
                int p0 = gst[sub * 66 + gi];
                int p1 = gst[sub * 66 + gi + 1];
                int key = keys_s[p0];
                if (key >= 0) {
                    const float* vp = &vals_s[b * VROW - base];
                    float s = 0.f;
                    for (int p = p0; p < p1; p++) s += vp[p];
                    atomicAdd(&out[(size_t)b * 32768 + key], s);
                }
            }
        }
        __syncthreads();   // before next sub overwrites vals
    }
}

extern "C" void kernel_launch(void* const* d_in, const int* in_sizes, int n_in,
                              void* d_out, int out_size) {
    const float* features  = (const float*)d_in[0];
    const float* W1        = (const float*)d_in[1];
    const float* W2        = (const float*)d_in[2];
    const float* W3        = (const float*)d_in[3];
    const float* eval_locs = (const float*)d_in[4];
    const int*   eval_idx  = (const int*)d_in[5];
    float*       out       = (float*)d_out;

    const int E = in_sizes[4] / 2;

    cudaFuncSetAttribute(quad_main, cudaFuncAttributeMaxDynamicSharedMemorySize,
                         SMEM_A_BYTES);

    detect_idx<<<1, 256>>>(eval_idx, E);
    convert_idx<<<(E + 255) / 256, 256>>>(eval_idx, E);
    prep_featT<<<dim3(N_IN / 32, 512 / 32), dim3(32, 8)>>>(features);
    zero_out<<<(BATCH * 32 * N_OUT) / 1024, 256>>>((float4*)out);
    quad_main<<<(E + 15) / 16, 256, SMEM_A_BYTES>>>(
        W1, W2, W3, eval_locs, out, E);
}

// round 13
// speedup vs baseline: 1.0502x; 1.0502x over previous
#include <cuda_runtime.h>
#include <math.h>

typedef unsigned long long u64;

#define FMA2(d, a, b, c) \
    asm("fma.rn.f32x2 %0, %1, %2, %3;" : "=l"(d) : "l"(a), "l"(b), "l"(c))
#define PACK2(d, lo, hi) \
    asm("mov.b64 %0, {%1, %2};" : "=l"(d) : "f"(lo), "f"(hi))
#define UNPACK2(lo, hi, d) \
    asm("mov.b64 {%0, %1}, %2;" : "=f"(lo), "=f"(hi) : "l"(d))
#define LDS_V2B64(a, b, addr) \
    asm volatile("ld.shared.v2.b64 {%0, %1}, [%2];" : "=l"(a), "=l"(b) : "r"(addr))

#define N_IN   4096
#define N_OUT  1024
#define BATCH  16
#define E_MAX  81920

__device__ float g_featT2[N_IN * 512];                 // [n][c*16+b]
__device__ int   g_seg[E_MAX];
__device__ int   g_src[E_MAX];

// ---------------- phase -1: idx normalize + zero output (one kernel) --------
// int64 little-endian with values < 2^31 => odd 32-bit words all zero.
__global__ void prep_idx(const int* __restrict__ idx32,
                         float4* __restrict__ out4, int E) {
    int local = 0;
    int n = min(E, 512);
    for (int m = threadIdx.x; m < n; m += 256)
        local |= idx32[4 * m + 1] | idx32[4 * m + 3];
    int any32 = __syncthreads_or(local);
    int m = blockIdx.x * 256 + threadIdx.x;
    if (m < E) {
        if (any32) { g_seg[m] = idx32[2 * m]; g_src[m] = idx32[2 * m + 1]; }
        else       { g_seg[m] = idx32[4 * m]; g_src[m] = idx32[4 * m + 2]; }
    }
    if (m < (BATCH * 32 * N_OUT) / 4)      // zero-init out (poisoned 0xAA)
        out4[m] = make_float4(0.f, 0.f, 0.f, 0.f);
}

// ---------------- phase 0: tiled permute feat[b][c][n] -> featT2[n][c*16+b]
__global__ void prep_featT(const float* __restrict__ feat) {
    __shared__ float tile[32][33];
    int n0  = blockIdx.x * 32;
    int cb0 = blockIdx.y * 32;
    int tx = threadIdx.x, ty = threadIdx.y;       // 32 x 8
    #pragma unroll
    for (int i = ty; i < 32; i += 8) {
        int cb = cb0 + i;
        int row = (cb & 15) * 32 + (cb >> 4);     // b*32 + c
        tile[i][tx] = feat[(size_t)row * N_IN + n0 + tx];
    }
    __syncthreads();
    #pragma unroll
    for (int i = ty; i < 32; i += 8)
        g_featT2[(size_t)(n0 + i) * 512 + cb0 + tx] = tile[tx][i];
}

// ---------------- phase A (fused: MLP + filter + apply + segment reduce) ----
// 256 threads, 16 edges/block, 2 blocks/SM. smem (floats):
//  h1 [16][64]     @0      (1024)
//  h2t[64][20]     @1024   (1280)
//  W2s[64][64]     @2304   (4096)
//  g  [8][16][36]  @6400   (4608)   <- overlaid by vals[16][264] after apply
//  filt[8][32][36] @11008  (9216)
//  locs[32]        @20224
//  goff[512] int   @20256
//  keys[512] int   @20768
//  gstart[2][66]+ng[2] int @21280
#define OFF_H1   0
#define OFF_H2T  1024
#define OFF_W2S  2304
#define OFF_G    6400
#define OFF_F    11008
#define OFF_LOCS 20224
#define OFF_GOFF 20256
#define OFF_KEYS 20768
#define OFF_GST  21280
#define SMEM_A_FLOATS 21416
#define SMEM_A_BYTES  (SMEM_A_FLOATS * 4)
#define VROW 264

__global__ __launch_bounds__(256, 2) void quad_main(
    const float* __restrict__ W1, const float* __restrict__ W2,
    const float* __restrict__ W3, const float* __restrict__ eval_locs,
    float* __restrict__ out, int E)
{
    extern __shared__ float sm[];
    float* h1_s   = sm + OFF_H1;
    float* h2t    = sm + OFF_H2T;
    float* W2s    = sm + OFF_W2S;
    float* g_s    = sm + OFF_G;
    float* vals_s = sm + OFF_G;        // overlay after apply
    float* f_s    = sm + OFF_F;
    float* locs   = sm + OFF_LOCS;
    int*   goff   = (int*)(sm + OFF_GOFF);
    int*   keys_s = (int*)(sm + OFF_KEYS);
    int*   gst    = (int*)(sm + OFF_GST);       // [2][66]
    int*   ng_s   = (int*)(sm + OFF_GST) + 132; // [2]
    const unsigned smb = (unsigned)__cvta_generic_to_shared(sm);

    const int t   = threadIdx.x;
    const int e0  = blockIdx.x * 16;
    const int net = min(16, E - e0);
    const int mb  = blockIdx.x * 512;   // flat vals base for this block

    if (t < 2 * net) locs[t] = eval_locs[2 * e0 + t];

    // stage W2 into smem (coalesced, once per block)
    #pragma unroll
    for (int r = 0; r < 16; r++)
        W2s[t + 256 * r] = W2[t + 256 * r];

    // gather offsets per (e, ci) AND scramble keys per flat pos p
    #pragma unroll
    for (int r = 0; r < 2; r++) {
        int p = t + 256 * r;              // 0..511
        int key = -1;
        if (p < net * 32) {
            int m  = mb + p;
            int c  = m / E;
            int rr = m - c * E;
            goff[p] = g_src[rr] * 512 + c * 16;
            key = (c << 10) + g_seg[rr];
        }
        keys_s[p] = key;
    }
    __syncthreads();

    // warps 0/1: run-boundary scan of keys for sub 0/1
    if (t < 64) {
        int sub  = t >> 5, l = t & 31;
        int base = sub * 256;
        int cnt = 0, st[8];
        #pragma unroll
        for (int i = 0; i < 8; i++) {
            int p = base + l * 8 + i;
            int kprev = (p == base) ? 0x7fffffff : keys_s[p - 1];
            if (keys_s[p] != kprev) st[cnt++] = p;
        }
        unsigned off = (unsigned)cnt;
        #pragma unroll
        for (int d = 1; d < 32; d <<= 1) {
            unsigned v = __shfl_up_sync(0xffffffffu, off, d);
            if (l >= d) off += v;
        }
        int excl = (int)off - cnt;
        for (int i = 0; i < cnt; i++) gst[sub * 66 + excl + i] = st[i];
        if (l == 31) { ng_s[sub] = (int)off; gst[sub * 66 + (int)off] = base + 256; }
    }

    // h1[e][j] = sin(loc_e . W1[:,j])   (0 for padded edges)
    #pragma unroll
    for (int r = 0; r < 4; r++) {
        int id = t + 256 * r;             // 0..1023
        int e = id >> 6, j = id & 63;
        float v = 0.f;
        if (e < net)
            v = __sinf(locs[2 * e] * W1[j] + locs[2 * e + 1] * W1[64 + j]);
        h1_s[id] = v;
    }
    __syncthreads();

    // ---- h2 (f32x2): thread owns (e = t>>4, cols j0..j0+3); writes h2t[j][e]
    {
        const int e  = t >> 4;
        const int j0 = (t & 15) * 4;
        u64 aA = 0ull, aB = 0ull;
        #pragma unroll
        for (int k4 = 0; k4 < 64; k4 += 4) {
            float4 hv = *(const float4*)&h1_s[e * 64 + k4];
            float hs[4] = {hv.x, hv.y, hv.z, hv.w};
            #pragma unroll
            for (int kk = 0; kk < 4; kk++) {
                u64 hh; PACK2(hh, hs[kk], hs[kk]);
                u64 w01, w23;
                LDS_V2B64(w01, w23, smb + (OFF_W2S + (k4 + kk) * 64 + j0) * 4);
                FMA2(aA, hh, w01, aA);
                FMA2(aB, hh, w23, aB);
            }
        }
        float s0, s1, s2, s3;
        UNPACK2(s0, s1, aA);
        UNPACK2(s2, s3, aB);
        s0 = __sinf(s0); s1 = __sinf(s1); s2 = __sinf(s2); s3 = __sinf(s3);
        if (e >= net) { s0 = s1 = s2 = s3 = 0.f; }
        h2t[(j0 + 0) * 20 + e] = s0;
        h2t[(j0 + 1) * 20 + e] = s1;
        h2t[(j0 + 2) * 20 + e] = s2;
        h2t[(j0 + 3) * 20 + e] = s3;
    }
    __syncthreads();

    // ---- filter gen (f32x2): thread owns 4 cols {4t..4t+3}, all 16 edges.
    u64 acc[4][8];
    #pragma unroll
    for (int c = 0; c < 4; c++)
        #pragma unroll
        for (int p = 0; p < 8; p++) acc[c][p] = 0ull;

    const float4* w3p4 = (const float4*)W3 + t;     // row stride 256 float4
    float4 wcur = w3p4[0];

    #pragma unroll 8
    for (int k = 0; k < 64; k++) {
        float4 wnext = (k < 63) ? w3p4[(k + 1) * 256] : wcur;
        u64 wa, wb, wc, wd;
        PACK2(wa, wcur.x, wcur.x);
        PACK2(wb, wcur.y, wcur.y);
        PACK2(wc, wcur.z, wcur.z);
        PACK2(wd, wcur.w, wcur.w);
        const unsigned ha = smb + (OFF_H2T + k * 20) * 4;
        u64 hp[8];
        LDS_V2B64(hp[0], hp[1], ha);
        LDS_V2B64(hp[2], hp[3], ha + 16);
        LDS_V2B64(hp[4], hp[5], ha + 32);
        LDS_V2B64(hp[6], hp[7], ha + 48);
        #pragma unroll
        for (int p = 0; p < 8; p++) {
            FMA2(acc[0][p], wa, hp[p], acc[0][p]);
            FMA2(acc[1][p], wb, hp[p], acc[1][p]);
            FMA2(acc[2][p], wc, hp[p], acc[2][p]);
            FMA2(acc[3][p], wd, hp[p], acc[3][p]);
        }
        wcur = wnext;
    }

    // mappings
    const int fci = t >> 3;              // filt store: col 4t -> ci
    const int fco = (t & 7) * 4;
    const int ea  = t >> 5;              // apply: edge within sub (0..7)
    const int b0  = ((t >> 2) & 7) * 2;  //        2 batches
    const int j0  = (t & 3) * 8;         //        8 consecutive co

    #pragma unroll
    for (int sub = 0; sub < 2; sub++) {
        const int es0 = sub * 8;

        // staged gather of 8 edges: g[e][b][ci]
        #pragma unroll
        for (int r = 0; r < 16; r++) {
            int i  = t + 256 * r;             // 0..4095
            int p8 = i >> 4;                  // (e,ci) 0..255
            int b  = i & 15;
            int e  = p8 >> 5, ci = p8 & 31;
            float v = (es0 + e < net) ? g_featT2[goff[(es0 + e) * 32 + ci] + b] : 0.f;
            g_s[e * 576 + b * 36 + ci] = v;
        }
        // store this sub's filters: edge pairs 4*sub..4*sub+3
        #pragma unroll
        for (int p = 0; p < 4; p++) {
            int pp = sub * 4 + p;
            float x0, x1, y0, y1, z0, z1, w0, w1;
            UNPACK2(x0, x1, acc[0][pp]);
            UNPACK2(y0, y1, acc[1][pp]);
            UNPACK2(z0, z1, acc[2][pp]);
            UNPACK2(w0, w1, acc[3][pp]);
            *(float4*)&f_s[(2 * p)     * 1152 + fci * 36 + fco] = make_float4(x0, y0, z0, w0);
            *(float4*)&f_s[(2 * p + 1) * 1152 + fci * 36 + fco] = make_float4(x1, y1, z1, w1);
        }
        __syncthreads();

        // apply (f32x2): 2 batches x 8 co per thread, one edge
        u64 a0[4] = {0ull, 0ull, 0ull, 0ull};
        u64 a1[4] = {0ull, 0ull, 0ull, 0ull};
        if (es0 + ea < net) {
            const float* gp0 = &g_s[ea * 576 + b0 * 36];
            const float* gp1 = gp0 + 36;
            const unsigned fpa = smb + (OFF_F + ea * 1152 + j0) * 4;
            #pragma unroll
            for (int ci4 = 0; ci4 < 32; ci4 += 4) {
                float4 gv0 = *(const float4*)&gp0[ci4];
                float4 gv1 = *(const float4*)&gp1[ci4];
                float g0v[4] = {gv0.x, gv0.y, gv0.z, gv0.w};
                float g1v[4] = {gv1.x, gv1.y, gv1.z, gv1.w};
                #pragma unroll
                for (int kk = 0; kk < 4; kk++) {
                    u64 f01, f23, f45, f67;
                    LDS_V2B64(f01, f23, fpa + (ci4 + kk) * 144);
                    LDS_V2B64(f45, f67, fpa + (ci4 + kk) * 144 + 16);
                    u64 d0; PACK2(d0, g0v[kk], g0v[kk]);
                    FMA2(a0[0], d0, f01, a0[0]);
                    FMA2(a0[1], d0, f23, a0[1]);
                    FMA2(a0[2], d0, f45, a0[2]);
                    FMA2(a0[3], d0, f67, a0[3]);
                    u64 d1; PACK2(d1, g1v[kk], g1v[kk]);
                    FMA2(a1[0], d1, f01, a1[0]);
                    FMA2(a1[1], d1, f23, a1[1]);
                    FMA2(a1[2], d1, f45, a1[2]);
                    FMA2(a1[3], d1, f67, a1[3]);
                }
            }
        }
        __syncthreads();   // all reads of g_s / f_s complete

        // dump vals to smem (overlay g_s): vals[b][ea*32 + j0 .. +7]
        {
            float* vp0 = &vals_s[b0 * VROW + ea * 32 + j0];
            float* vp1 = vp0 + VROW;
            ulonglong2 s0a; s0a.x = a0[0]; s0a.y = a0[1];
            ulonglong2 s0b; s0b.x = a0[2]; s0b.y = a0[3];
            ulonglong2 s1a; s1a.x = a1[0]; s1a.y = a1[1];
            ulonglong2 s1b; s1b.x = a1[2]; s1b.y = a1[3];
            *(ulonglong2*)vp0       = s0a;
            *(ulonglong2*)(vp0 + 4) = s0b;
            *(ulonglong2*)vp1       = s1a;
            *(ulonglong2*)(vp1 + 4) = s1b;
        }
        __syncthreads();   // vals ready

        // segment reduce: one (b, group) per task -> single atomicAdd
        {
            const int ng = ng_s[sub];
            const int base = sub * 256;
            for (int task = t; task < 16 * ng; task += 256) {
                int b  = task / ng;
                int gi = task - b * ng;
                int p0 = gst[sub * 66 + gi];
                int p1 = gst[sub * 66 + gi + 1];
                int key = keys_s[p0];
                if (key >= 0) {
                    const float* vp = &vals_s[b * VROW - base];
                    float s = 0.f;
                    for (int p = p0; p < p1; p++) s += vp[p];
                    atomicAdd(&out[(size_t)b * 32768 + key], s);
                }
            }
        }
        __syncthreads();   // before next sub overwrites vals/g_s
    }
}

extern "C" void kernel_launch(void* const* d_in, const int* in_sizes, int n_in,
                              void* d_out, int out_size) {
    const float* features  = (const float*)d_in[0];
    const float* W1        = (const float*)d_in[1];
    const float* W2        = (const float*)d_in[2];
    const float* W3        = (const float*)d_in[3];
    const float* eval_locs = (const float*)d_in[4];
    const int*   eval_idx  = (const int*)d_in[5];
    float*       out       = (float*)d_out;

    const int E = in_sizes[4] / 2;

    cudaFuncSetAttribute(quad_main, cudaFuncAttributeMaxDynamicSharedMemorySize,
                         SMEM_A_BYTES);

    int prep_items = E > (BATCH * 32 * N_OUT) / 4 ? E : (BATCH * 32 * N_OUT) / 4;
    prep_idx<<<(prep_items + 255) / 256, 256>>>(eval_idx, (float4*)out, E);
    prep_featT<<<dim3(N_IN / 32, 512 / 32), dim3(32, 8)>>>(features);
    quad_main<<<(E + 15) / 16, 256, SMEM_A_BYTES>>>(
        W1, W2, W3, eval_locs, out, E);
}

// round 14
// speedup vs baseline: 1.2585x; 1.1983x over previous
#include <cuda_runtime.h>
#include <math.h>

typedef unsigned long long u64;

#define FMA2(d, a, b, c) \
    asm("fma.rn.f32x2 %0, %1, %2, %3;" : "=l"(d) : "l"(a), "l"(b), "l"(c))
#define PACK2(d, lo, hi) \
    asm("mov.b64 %0, {%1, %2};" : "=l"(d) : "f"(lo), "f"(hi))
#define UNPACK2(lo, hi, d) \
    asm("mov.b64 {%0, %1}, %2;" : "=f"(lo), "=f"(hi) : "l"(d))
#define LDS_V2B64(a, b, addr) \
    asm volatile("ld.shared.v2.b64 {%0, %1}, [%2];" : "=l"(a), "=l"(b) : "r"(addr))
#define CVT_TF32(u, f) \
    asm("cvt.rna.tf32.f32 %0, %1;" : "=r"(u) : "f"(f))
#define MMA_TF32(d, a0, a1, a2, a3, b0, b1) \
    asm("mma.sync.aligned.m16n8k8.row.col.f32.tf32.tf32.f32 " \
        "{%0,%1,%2,%3},{%4,%5,%6,%7},{%8,%9},{%0,%1,%2,%3};" \
        : "+f"(d[0]), "+f"(d[1]), "+f"(d[2]), "+f"(d[3]) \
        : "r"(a0), "r"(a1), "r"(a2), "r"(a3), "r"(b0), "r"(b1))

#define N_IN   4096
#define N_OUT  1024
#define BATCH  16
#define E_MAX  81920

__device__ float g_featT2[N_IN * 512];                 // [n][c*16+b]
__device__ float g_W3t[65536];                         // tf32 fragment-ordered W3
__device__ int   g_seg[E_MAX];
__device__ int   g_src[E_MAX];

// ---------------- phase -1: idx normalize + zero output (one kernel) --------
__global__ void prep_idx(const int* __restrict__ idx32,
                         float4* __restrict__ out4, int E) {
    int local = 0;
    int n = min(E, 512);
    for (int m = threadIdx.x; m < n; m += 256)
        local |= idx32[4 * m + 1] | idx32[4 * m + 3];
    int any32 = __syncthreads_or(local);
    int m = blockIdx.x * 256 + threadIdx.x;
    if (m < E) {
        if (any32) { g_seg[m] = idx32[2 * m]; g_src[m] = idx32[2 * m + 1]; }
        else       { g_seg[m] = idx32[4 * m]; g_src[m] = idx32[4 * m + 2]; }
    }
    if (m < (BATCH * 32 * N_OUT) / 4)
        out4[m] = make_float4(0.f, 0.f, 0.f, 0.f);
}

// ---------------- phase -0.8: W3 -> tf32 fragment-ordered copy --------------
// chunk (ks, gt) of 64 floats: elem 2l+h = tf32(W3[ks*8 + (l&3) + 4h][gt*8 + l/4])
__global__ void prep_w3t(const float* __restrict__ W3) {
    int i = blockIdx.x * 256 + threadIdx.x;   // 0..65535
    int ks  = i >> 13;
    int rem = i & 8191;
    int gt  = rem >> 6;
    int q   = rem & 63;
    int l   = q >> 1, h = q & 1;
    float v = W3[(ks * 8 + (l & 3) + 4 * h) * 1024 + gt * 8 + (l >> 2)];
    unsigned u; CVT_TF32(u, v);
    g_W3t[i] = __uint_as_float(u);
}

// ---------------- phase 0: tiled permute feat[b][c][n] -> featT2[n][c*16+b]
__global__ void prep_featT(const float* __restrict__ feat) {
    __shared__ float tile[32][33];
    int n0  = blockIdx.x * 32;
    int cb0 = blockIdx.y * 32;
    int tx = threadIdx.x, ty = threadIdx.y;       // 32 x 8
    #pragma unroll
    for (int i = ty; i < 32; i += 8) {
        int cb = cb0 + i;
        int row = (cb & 15) * 32 + (cb >> 4);     // b*32 + c
        tile[i][tx] = feat[(size_t)row * N_IN + n0 + tx];
    }
    __syncthreads();
    #pragma unroll
    for (int i = ty; i < 32; i += 8)
        g_featT2[(size_t)(n0 + i) * 512 + cb0 + tx] = tile[tx][i];
}

// ---------------- phase A (fused; tf32 tensor-core filter gen) --------------
// 256 threads, 16 edges/block, 2 blocks/SM. smem (floats):
//  h1 [16][64]     @0      (1024)
//  h2e[16][68]     @1024   (1088)   row-major, pad 68
//  W2s[64][64]     @2304   (4096)
//  g  [8][16][36]  @6400   (4608)   <- overlaid by vals[16][264] after apply
//  filt[8][32][36] @11008  (9216)
//  locs[32]        @20224
//  goff[512] int   @20256
//  keys[512] int   @20768
//  gstart[2][66]+ng[2] int @21280
#define OFF_H1   0
#define OFF_H2E  1024
#define OFF_W2S  2304
#define OFF_G    6400
#define OFF_F    11008
#define OFF_LOCS 20224
#define OFF_GOFF 20256
#define OFF_KEYS 20768
#define OFF_GST  21280
#define SMEM_A_FLOATS 21416
#define SMEM_A_BYTES  (SMEM_A_FLOATS * 4)
#define VROW 264

__global__ __launch_bounds__(256, 2) void quad_main(
    const float* __restrict__ W1, const float* __restrict__ W2,
    const float* __restrict__ eval_locs, float* __restrict__ out, int E)
{
    extern __shared__ float sm[];
    float* h1_s   = sm + OFF_H1;
    float* h2e    = sm + OFF_H2E;
    float* W2s    = sm + OFF_W2S;
    float* g_s    = sm + OFF_G;
    float* vals_s = sm + OFF_G;        // overlay after apply
    float* f_s    = sm + OFF_F;
    float* locs   = sm + OFF_LOCS;
    int*   goff   = (int*)(sm + OFF_GOFF);
    int*   keys_s = (int*)(sm + OFF_KEYS);
    int*   gst    = (int*)(sm + OFF_GST);       // [2][66]
    int*   ng_s   = (int*)(sm + OFF_GST) + 132; // [2]
    const unsigned smb = (unsigned)__cvta_generic_to_shared(sm);

    const int t   = threadIdx.x;
    const int e0  = blockIdx.x * 16;
    const int net = min(16, E - e0);
    const int mb  = blockIdx.x * 512;   // flat vals base for this block

    if (t < 2 * net) locs[t] = eval_locs[2 * e0 + t];

    // stage W2 into smem (coalesced, once per block)
    #pragma unroll
    for (int r = 0; r < 16; r++)
        W2s[t + 256 * r] = W2[t + 256 * r];

    // gather offsets per (e, ci) AND scramble keys per flat pos p
    #pragma unroll
    for (int r = 0; r < 2; r++) {
        int p = t + 256 * r;              // 0..511
        int key = -1;
        if (p < net * 32) {
            int m  = mb + p;
            int c  = m / E;
            int rr = m - c * E;
            goff[p] = g_src[rr] * 512 + c * 16;
            key = (c << 10) + g_seg[rr];
        }
        keys_s[p] = key;
    }
    __syncthreads();

    // warps 0/1: run-boundary scan of keys for sub 0/1
    if (t < 64) {
        int sub  = t >> 5, l = t & 31;
        int base = sub * 256;
        int cnt = 0, st[8];
        #pragma unroll
        for (int i = 0; i < 8; i++) {
            int p = base + l * 8 + i;
            int kprev = (p == base) ? 0x7fffffff : keys_s[p - 1];
            if (keys_s[p] != kprev) st[cnt++] = p;
        }
        unsigned off = (unsigned)cnt;
        #pragma unroll
        for (int d = 1; d < 32; d <<= 1) {
            unsigned v = __shfl_up_sync(0xffffffffu, off, d);
            if (l >= d) off += v;
        }
        int excl = (int)off - cnt;
        for (int i = 0; i < cnt; i++) gst[sub * 66 + excl + i] = st[i];
        if (l == 31) { ng_s[sub] = (int)off; gst[sub * 66 + (int)off] = base + 256; }
    }

    // h1[e][j] = sin(loc_e . W1[:,j])   (0 for padded edges)
    #pragma unroll
    for (int r = 0; r < 4; r++) {
        int id = t + 256 * r;             // 0..1023
        int e = id >> 6, j = id & 63;
        float v = 0.f;
        if (e < net)
            v = __sinf(locs[2 * e] * W1[j] + locs[2 * e + 1] * W1[64 + j]);
        h1_s[id] = v;
    }
    __syncthreads();

    // ---- h2 (f32x2): thread owns (e = t>>4, cols j0..j0+3); writes h2e[e][j]
    {
        const int e  = t >> 4;
        const int j0 = (t & 15) * 4;
        u64 aA = 0ull, aB = 0ull;
        #pragma unroll
        for (int k4 = 0; k4 < 64; k4 += 4) {
            float4 hv = *(const float4*)&h1_s[e * 64 + k4];
            float hs[4] = {hv.x, hv.y, hv.z, hv.w};
            #pragma unroll
            for (int kk = 0; kk < 4; kk++) {
                u64 hh; PACK2(hh, hs[kk], hs[kk]);
                u64 w01, w23;
                LDS_V2B64(w01, w23, smb + (OFF_W2S + (k4 + kk) * 64 + j0) * 4);
                FMA2(aA, hh, w01, aA);
                FMA2(aB, hh, w23, aB);
            }
        }
        float s0, s1, s2, s3;
        UNPACK2(s0, s1, aA);
        UNPACK2(s2, s3, aB);
        s0 = __sinf(s0); s1 = __sinf(s1); s2 = __sinf(s2); s3 = __sinf(s3);
        if (e >= net) { s0 = s1 = s2 = s3 = 0.f; }
        *(float4*)&h2e[e * 68 + j0] = make_float4(s0, s1, s2, s3);
    }
    __syncthreads();

    // ---- filter gen on tensor cores (tf32 mma.sync m16n8k8) ----
    // warp w owns cols [w*128, w*128+128): 16 n-tiles x 8 k-steps.
    const int lane = t & 31;
    const int w    = t >> 5;
    const int rA   = lane >> 2;
    const int tig  = lane & 3;

    float dacc[16][4];
    #pragma unroll
    for (int ti = 0; ti < 16; ti++) {
        dacc[ti][0] = 0.f; dacc[ti][1] = 0.f;
        dacc[ti][2] = 0.f; dacc[ti][3] = 0.f;
    }

    #pragma unroll
    for (int ks = 0; ks < 8; ks++) {
        const int kk = ks * 8 + tig;
        unsigned A0, A1, A2, A3;
        CVT_TF32(A0, h2e[rA * 68 + kk]);
        CVT_TF32(A1, h2e[(rA + 8) * 68 + kk]);
        CVT_TF32(A2, h2e[rA * 68 + kk + 4]);
        CVT_TF32(A3, h2e[(rA + 8) * 68 + kk + 4]);
        const float2* bp = (const float2*)(g_W3t + ((ks << 7) + (w << 4)) * 64) + lane;
        #pragma unroll
        for (int ti = 0; ti < 16; ti++) {
            float2 bv = bp[ti * 32];
            unsigned B0 = __float_as_uint(bv.x);
            unsigned B1 = __float_as_uint(bv.y);
            MMA_TF32(dacc[ti], A0, A1, A2, A3, B0, B1);
        }
    }

    // apply mappings
    const int ea  = t >> 5;              // apply: edge within sub (0..7)
    const int b0  = ((t >> 2) & 7) * 2;  //        2 batches
    const int j0  = (t & 3) * 8;         //        8 consecutive co

    #pragma unroll
    for (int sub = 0; sub < 2; sub++) {
        const int es0 = sub * 8;

        // staged gather of 8 edges: g[e][b][ci]
        #pragma unroll
        for (int r = 0; r < 16; r++) {
            int i  = t + 256 * r;             // 0..4095
            int p8 = i >> 4;                  // (e,ci) 0..255
            int b  = i & 15;
            int e  = p8 >> 5, ci = p8 & 31;
            float v = (es0 + e < net) ? g_featT2[goff[(es0 + e) * 32 + ci] + b] : 0.f;
            g_s[e * 576 + b * 36 + ci] = v;
        }
        // store this sub's filters from D fragments:
        // sub 0 -> rows rA (c0,c1); sub 1 -> rows rA+8 (c2,c3), local edge = rA
        #pragma unroll
        for (int ti = 0; ti < 16; ti++) {
            int col = (w << 7) + ti * 8 + tig * 2;
            int ci  = col >> 5, co = col & 31;
            float2 v;
            v.x = dacc[ti][sub * 2];
            v.y = dacc[ti][sub * 2 + 1];
            *(float2*)&f_s[rA * 1152 + ci * 36 + co] = v;
        }
        __syncthreads();

        // apply (f32x2): 2 batches x 8 co per thread, one edge
        u64 a0[4] = {0ull, 0ull, 0ull, 0ull};
        u64 a1[4] = {0ull, 0ull, 0ull, 0ull};
        if (es0 + ea < net) {
            const float* gp0 = &g_s[ea * 576 + b0 * 36];
            const float* gp1 = gp0 + 36;
            const unsigned fpa = smb + (OFF_F + ea * 1152 + j0) * 4;
            #pragma unroll
            for (int ci4 = 0; ci4 < 32; ci4 += 4) {
                float4 gv0 = *(const float4*)&gp0[ci4];
                float4 gv1 = *(const float4*)&gp1[ci4];
                float g0v[4] = {gv0.x, gv0.y, gv0.z, gv0.w};
                float g1v[4] = {gv1.x, gv1.y, gv1.z, gv1.w};
                #pragma unroll
                for (int kk = 0; kk < 4; kk++) {
                    u64 f01, f23, f45, f67;
                    LDS_V2B64(f01, f23, fpa + (ci4 + kk) * 144);
                    LDS_V2B64(f45, f67, fpa + (ci4 + kk) * 144 + 16);
                    u64 d0; PACK2(d0, g0v[kk], g0v[kk]);
                    FMA2(a0[0], d0, f01, a0[0]);
                    FMA2(a0[1], d0, f23, a0[1]);
                    FMA2(a0[2], d0, f45, a0[2]);
                    FMA2(a0[3], d0, f67, a0[3]);
                    u64 d1; PACK2(d1, g1v[kk], g1v[kk]);
                    FMA2(a1[0], d1, f01, a1[0]);
                    FMA2(a1[1], d1, f23, a1[1]);
                    FMA2(a1[2], d1, f45, a1[2]);
                    FMA2(a1[3], d1, f67, a1[3]);
                }
            }
        }
        __syncthreads();   // all reads of g_s / f_s complete

        // dump vals to smem (overlay g_s): vals[b][ea*32 + j0 .. +7]
        {
            float* vp0 = &vals_s[b0 * VROW + ea * 32 + j0];
            float* vp1 = vp0 + VROW;
            ulonglong2 s0a; s0a.x = a0[0]; s0a.y = a0[1];
            ulonglong2 s0b; s0b.x = a0[2]; s0b.y = a0[3];
            ulonglong2 s1a; s1a.x = a1[0]; s1a.y = a1[1];
            ulonglong2 s1b; s1b.x = a1[2]; s1b.y = a1[3];
            *(ulonglong2*)vp0       = s0a;
            *(ulonglong2*)(vp0 + 4) = s0b;
            *(ulonglong2*)vp1       = s1a;
            *(ulonglong2*)(vp1 + 4) = s1b;
        }
        __syncthreads();   // vals ready

        // segment reduce: one (b, group) per task -> single atomicAdd
        {
            const int ng = ng_s[sub];
            const int base = sub * 256;
            for (int task = t; task < 16 * ng; task += 256) {
                int b  = task / ng;
                int gi = task - b * ng;
                int p0 = gst[sub * 66 + gi];
                int p1 = gst[sub * 66 + gi + 1];
                int key = keys_s[p0];
                if (key >= 0) {
                    const float* vp = &vals_s[b * VROW - base];
                    float s = 0.f;
                    for (int p = p0; p < p1; p++) s += vp[p];
                    atomicAdd(&out[(size_t)b * 32768 + key], s);
                }
            }
        }
        __syncthreads();   // before next sub overwrites vals/g_s
    }
}

extern "C" void kernel_launch(void* const* d_in, const int* in_sizes, int n_in,
                              void* d_out, int out_size) {
    const float* features  = (const float*)d_in[0];
    const float* W1        = (const float*)d_in[1];
    const float* W2        = (const float*)d_in[2];
    const float* W3        = (const float*)d_in[3];
    const float* eval_locs = (const float*)d_in[4];
    const int*   eval_idx  = (const int*)d_in[5];
    float*       out       = (float*)d_out;

    const int E = in_sizes[4] / 2;

    cudaFuncSetAttribute(quad_main, cudaFuncAttributeMaxDynamicSharedMemorySize,
                         SMEM_A_BYTES);

    int prep_items = E > (BATCH * 32 * N_OUT) / 4 ? E : (BATCH * 32 * N_OUT) / 4;
    prep_idx<<<(prep_items + 255) / 256, 256>>>(eval_idx, (float4*)out, E);
    prep_w3t<<<256, 256>>>(W3);
    prep_featT<<<dim3(N_IN / 32, 512 / 32), dim3(32, 8)>>>(features);
    quad_main<<<(E + 15) / 16, 256, SMEM_A_BYTES>>>(
        W1, W2, eval_locs, out, E);
}

// round 15
// speedup vs baseline: 1.2968x; 1.0304x over previous
#include <cuda_runtime.h>
#include <math.h>

typedef unsigned long long u64;

#define FMA2(d, a, b, c) \
    asm("fma.rn.f32x2 %0, %1, %2, %3;" : "=l"(d) : "l"(a), "l"(b), "l"(c))
#define PACK2(d, lo, hi) \
    asm("mov.b64 %0, {%1, %2};" : "=l"(d) : "f"(lo), "f"(hi))
#define UNPACK2(lo, hi, d) \
    asm("mov.b64 {%0, %1}, %2;" : "=f"(lo), "=f"(hi) : "l"(d))
#define LDS_V2B64(a, b, addr) \
    asm volatile("ld.shared.v2.b64 {%0, %1}, [%2];" : "=l"(a), "=l"(b) : "r"(addr))
#define LDS_B64(a, addr) \
    asm volatile("ld.shared.b64 %0, [%1];" : "=l"(a) : "r"(addr))
#define CVT_TF32(u, f) \
    asm("cvt.rna.tf32.f32 %0, %1;" : "=r"(u) : "f"(f))
#define MMA_TF32(d, a0, a1, a2, a3, b0, b1) \
    asm("mma.sync.aligned.m16n8k8.row.col.f32.tf32.tf32.f32 " \
        "{%0,%1,%2,%3},{%4,%5,%6,%7},{%8,%9},{%0,%1,%2,%3};" \
        : "+f"(d[0]), "+f"(d[1]), "+f"(d[2]), "+f"(d[3]) \
        : "r"(a0), "r"(a1), "r"(a2), "r"(a3), "r"(b0), "r"(b1))

#define N_IN   4096
#define N_OUT  1024
#define BATCH  16
#define E_MAX  81920

__device__ float g_featT2[N_IN * 512];                 // [n][c*16+b]
__device__ float g_W3t[65536];                         // tf32 fragment-ordered W3
__device__ int   g_seg[E_MAX];
__device__ int   g_src[E_MAX];

// ---------------- phase -1: idx normalize + zero output (one kernel) --------
__global__ void prep_idx(const int* __restrict__ idx32,
                         float4* __restrict__ out4, int E) {
    int local = 0;
    int n = min(E, 512);
    for (int m = threadIdx.x; m < n; m += 256)
        local |= idx32[4 * m + 1] | idx32[4 * m + 3];
    int any32 = __syncthreads_or(local);
    int m = blockIdx.x * 256 + threadIdx.x;
    if (m < E) {
        if (any32) { g_seg[m] = idx32[2 * m]; g_src[m] = idx32[2 * m + 1]; }
        else       { g_seg[m] = idx32[4 * m]; g_src[m] = idx32[4 * m + 2]; }
    }
    if (m < (BATCH * 32 * N_OUT) / 4)
        out4[m] = make_float4(0.f, 0.f, 0.f, 0.f);
}

// ---------------- phase -0.8: W3 -> tf32 fragment-ordered copy --------------
__global__ void prep_w3t(const float* __restrict__ W3) {
    int i = blockIdx.x * 256 + threadIdx.x;   // 0..65535
    int ks  = i >> 13;
    int rem = i & 8191;
    int gt  = rem >> 6;
    int q   = rem & 63;
    int l   = q >> 1, h = q & 1;
    float v = W3[(ks * 8 + (l & 3) + 4 * h) * 1024 + gt * 8 + (l >> 2)];
    unsigned u; CVT_TF32(u, v);
    g_W3t[i] = __uint_as_float(u);
}

// ---------------- phase 0: tiled permute feat[b][c][n] -> featT2[n][c*16+b]
__global__ void prep_featT(const float* __restrict__ feat) {
    __shared__ float tile[32][33];
    int n0  = blockIdx.x * 32;
    int cb0 = blockIdx.y * 32;
    int tx = threadIdx.x, ty = threadIdx.y;       // 32 x 8
    #pragma unroll
    for (int i = ty; i < 32; i += 8) {
        int cb = cb0 + i;
        int row = (cb & 15) * 32 + (cb >> 4);     // b*32 + c
        tile[i][tx] = feat[(size_t)row * N_IN + n0 + tx];
    }
    __syncthreads();
    #pragma unroll
    for (int i = ty; i < 32; i += 8)
        g_featT2[(size_t)(n0 + i) * 512 + cb0 + tx] = tile[tx][i];
}

// ---------------- phase A (fused; 512 threads for occupancy) ----------------
// 512 threads, 16 edges/block, 2 blocks/SM. smem identical to R14 layout.
#define OFF_H1   0
#define OFF_H2E  1024
#define OFF_W2S  2304
#define OFF_G    6400
#define OFF_F    11008
#define OFF_LOCS 20224
#define OFF_GOFF 20256
#define OFF_KEYS 20768
#define OFF_GST  21280
#define SMEM_A_FLOATS 21416
#define SMEM_A_BYTES  (SMEM_A_FLOATS * 4)
#define VROW 264

__global__ __launch_bounds__(512, 2) void quad_main(
    const float* __restrict__ W1, const float* __restrict__ W2,
    const float* __restrict__ eval_locs, float* __restrict__ out, int E)
{
    extern __shared__ float sm[];
    float* h1_s   = sm + OFF_H1;
    float* h2e    = sm + OFF_H2E;
    float* W2s    = sm + OFF_W2S;
    float* g_s    = sm + OFF_G;
    float* vals_s = sm + OFF_G;        // overlay after apply
    float* f_s    = sm + OFF_F;
    float* locs   = sm + OFF_LOCS;
    int*   goff   = (int*)(sm + OFF_GOFF);
    int*   keys_s = (int*)(sm + OFF_KEYS);
    int*   gst    = (int*)(sm + OFF_GST);       // [2][66]
    int*   ng_s   = (int*)(sm + OFF_GST) + 132; // [2]
    const unsigned smb = (unsigned)__cvta_generic_to_shared(sm);

    const int t   = threadIdx.x;
    const int e0  = blockIdx.x * 16;
    const int net = min(16, E - e0);
    const int mb  = blockIdx.x * 512;   // flat vals base for this block

    if (t < 2 * net) locs[t] = eval_locs[2 * e0 + t];

    // stage W2 into smem (coalesced, once per block)
    #pragma unroll
    for (int r = 0; r < 8; r++)
        W2s[t + 512 * r] = W2[t + 512 * r];

    // gather offsets per (e, ci) AND scramble keys per flat pos p
    {
        int p = t;                        // 0..511
        int key = -1;
        if (p < net * 32) {
            int m  = mb + p;
            int c  = m / E;
            int rr = m - c * E;
            goff[p] = g_src[rr] * 512 + c * 16;
            key = (c << 10) + g_seg[rr];
        }
        keys_s[p] = key;
    }
    __syncthreads();

    // warps 0/1: run-boundary scan of keys for sub 0/1
    if (t < 64) {
        int sub  = t >> 5, l = t & 31;
        int base = sub * 256;
        int cnt = 0, st[8];
        #pragma unroll
        for (int i = 0; i < 8; i++) {
            int p = base + l * 8 + i;
            int kprev = (p == base) ? 0x7fffffff : keys_s[p - 1];
            if (keys_s[p] != kprev) st[cnt++] = p;
        }
        unsigned off = (unsigned)cnt;
        #pragma unroll
        for (int d = 1; d < 32; d <<= 1) {
            unsigned v = __shfl_up_sync(0xffffffffu, off, d);
            if (l >= d) off += v;
        }
        int excl = (int)off - cnt;
        for (int i = 0; i < cnt; i++) gst[sub * 66 + excl + i] = st[i];
        if (l == 31) { ng_s[sub] = (int)off; gst[sub * 66 + (int)off] = base + 256; }
    }

    // h1[e][j] = sin(loc_e . W1[:,j])   (0 for padded edges)
    #pragma unroll
    for (int r = 0; r < 2; r++) {
        int id = t + 512 * r;             // 0..1023
        int e = id >> 6, j = id & 63;
        float v = 0.f;
        if (e < net)
            v = __sinf(locs[2 * e] * W1[j] + locs[2 * e + 1] * W1[64 + j]);
        h1_s[id] = v;
    }
    __syncthreads();

    // ---- h2 (f32x2): thread owns (e = t>>5, 2 cols j0 = (t&31)*2) -> h2e[e][j]
    {
        const int e  = t >> 5;
        const int j0 = (t & 31) * 2;
        u64 acc = 0ull;
        #pragma unroll 8
        for (int k = 0; k < 64; k++) {
            float hv = h1_s[e * 64 + k];
            u64 hh; PACK2(hh, hv, hv);
            u64 w;
            LDS_B64(w, smb + (OFF_W2S + k * 64 + j0) * 4);
            FMA2(acc, hh, w, acc);
        }
        float s0, s1;
        UNPACK2(s0, s1, acc);
        s0 = __sinf(s0); s1 = __sinf(s1);
        if (e >= net) { s0 = 0.f; s1 = 0.f; }
        *(float2*)&h2e[e * 68 + j0] = make_float2(s0, s1);
    }
    __syncthreads();

    // ---- filter gen on tensor cores (tf32 mma.sync m16n8k8) ----
    // warp w (0..15) owns cols [w*64, w*64+64): 8 n-tiles x 8 k-steps.
    const int lane = t & 31;
    const int w    = t >> 5;
    const int rA   = lane >> 2;
    const int tig  = lane & 3;

    float dacc[8][4];
    #pragma unroll
    for (int ti = 0; ti < 8; ti++) {
        dacc[ti][0] = 0.f; dacc[ti][1] = 0.f;
        dacc[ti][2] = 0.f; dacc[ti][3] = 0.f;
    }

    #pragma unroll
    for (int ks = 0; ks < 8; ks++) {
        const int kk = ks * 8 + tig;
        unsigned A0, A1, A2, A3;
        CVT_TF32(A0, h2e[rA * 68 + kk]);
        CVT_TF32(A1, h2e[(rA + 8) * 68 + kk]);
        CVT_TF32(A2, h2e[rA * 68 + kk + 4]);
        CVT_TF32(A3, h2e[(rA + 8) * 68 + kk + 4]);
        const float2* bp = (const float2*)(g_W3t + ((ks << 7) + (w << 3)) * 64) + lane;
        #pragma unroll
        for (int ti = 0; ti < 8; ti++) {
            float2 bv = bp[ti * 32];
            unsigned B0 = __float_as_uint(bv.x);
            unsigned B1 = __float_as_uint(bv.y);
            MMA_TF32(dacc[ti], A0, A1, A2, A3, B0, B1);
        }
    }

    // apply mappings
    const int ea  = t >> 6;              // apply: edge within sub (0..7)
    const int b0  = ((t >> 3) & 7) * 2;  //        2 batches
    const int j0  = (t & 7) * 4;         //        4 consecutive co

    #pragma unroll
    for (int sub = 0; sub < 2; sub++) {
        const int es0 = sub * 8;

        // staged gather of 8 edges: g[e][b][ci]
        #pragma unroll
        for (int r = 0; r < 8; r++) {
            int i  = t + 512 * r;             // 0..4095
            int p8 = i >> 4;                  // (e,ci) 0..255
            int b  = i & 15;
            int e  = p8 >> 5, ci = p8 & 31;
            float v = (es0 + e < net) ? g_featT2[goff[(es0 + e) * 32 + ci] + b] : 0.f;
            g_s[e * 576 + b * 36 + ci] = v;
        }
        // store this sub's filters from D fragments:
        // sub 0 -> rows rA (c0,c1); sub 1 -> rows rA+8 (c2,c3), local edge = rA
        #pragma unroll
        for (int ti = 0; ti < 8; ti++) {
            int col = (w << 6) + ti * 8 + tig * 2;
            int ci  = col >> 5, co = col & 31;
            float2 v;
            v.x = dacc[ti][sub * 2];
            v.y = dacc[ti][sub * 2 + 1];
            *(float2*)&f_s[rA * 1152 + ci * 36 + co] = v;
        }
        __syncthreads();

        // apply (f32x2): 2 batches x 4 co per thread, one edge
        u64 a00 = 0ull, a01 = 0ull, a10 = 0ull, a11 = 0ull;
        if (es0 + ea < net) {
            const float* gp0 = &g_s[ea * 576 + b0 * 36];
            const float* gp1 = gp0 + 36;
            const unsigned fpa = smb + (OFF_F + ea * 1152 + j0) * 4;
            #pragma unroll
            for (int ci4 = 0; ci4 < 32; ci4 += 4) {
                float4 gv0 = *(const float4*)&gp0[ci4];
                float4 gv1 = *(const float4*)&gp1[ci4];
                float g0v[4] = {gv0.x, gv0.y, gv0.z, gv0.w};
                float g1v[4] = {gv1.x, gv1.y, gv1.z, gv1.w};
                #pragma unroll
                for (int kk = 0; kk < 4; kk++) {
                    u64 f01, f23;
                    LDS_V2B64(f01, f23, fpa + (ci4 + kk) * 144);
                    u64 d0; PACK2(d0, g0v[kk], g0v[kk]);
                    FMA2(a00, d0, f01, a00);
                    FMA2(a01, d0, f23, a01);
                    u64 d1; PACK2(d1, g1v[kk], g1v[kk]);
                    FMA2(a10, d1, f01, a10);
                    FMA2(a11, d1, f23, a11);
                }
            }
        }
        __syncthreads();   // all reads of g_s / f_s complete

        // dump vals to smem (overlay g_s): vals[b][ea*32 + j0 .. +3]
        {
            float* vp0 = &vals_s[b0 * VROW + ea * 32 + j0];
            float* vp1 = vp0 + VROW;
            ulonglong2 s0; s0.x = a00; s0.y = a01;
            ulonglong2 s1; s1.x = a10; s1.y = a11;
            *(ulonglong2*)vp0 = s0;
            *(ulonglong2*)vp1 = s1;
        }
        __syncthreads();   // vals ready

        // segment reduce: one (b, group) per task -> single atomicAdd
        {
            const int ng = ng_s[sub];
            const int base = sub * 256;
            for (int task = t; task < 16 * ng; task += 512) {
                int b  = task / ng;
                int gi = task - b * ng;
                int p0 = gst[sub * 66 + gi];
                int p1 = gst[sub * 66 + gi + 1];
                int key = keys_s[p0];
                if (key >= 0) {
                    const float* vp = &vals_s[b * VROW - base];
                    float s = 0.f;
                    for (int p = p0; p < p1; p++) s += vp[p];
                    atomicAdd(&out[(size_t)b * 32768 + key], s);
                }
            }
        }
        __syncthreads();   // before next sub overwrites vals/g_s
    }
}

extern "C" void kernel_launch(void* const* d_in, const int* in_sizes, int n_in,
                              void* d_out, int out_size) {
    const float* features  = (const float*)d_in[0];
    const float* W1        = (const float*)d_in[1];
    const float* W2        = (const float*)d_in[2];
    const float* W3        = (const float*)d_in[3];
    const float* eval_locs = (const float*)d_in[4];
    const int*   eval_idx  = (const int*)d_in[5];
    float*       out       = (float*)d_out;

    const int E = in_sizes[4] / 2;

    cudaFuncSetAttribute(quad_main, cudaFuncAttributeMaxDynamicSharedMemorySize,
                         SMEM_A_BYTES);

    int prep_items = E > (BATCH * 32 * N_OUT) / 4 ? E : (BATCH * 32 * N_OUT) / 4;
    prep_idx<<<(prep_items + 255) / 256, 256>>>(eval_idx, (float4*)out, E);
    prep_w3t<<<256, 256>>>(W3);
    prep_featT<<<dim3(N_IN / 32, 512 / 32), dim3(32, 8)>>>(features);
    quad_main<<<(E + 15) / 16, 512, SMEM_A_BYTES>>>(
        W1, W2, eval_locs, out, E);
}